// round 5
// baseline (speedup 1.0000x reference)
#include <cuda_runtime.h>
#include <cstdint>

#define HID    1024
#define NBATCH 4
#define SEQ    2048
#define NHEAD  16
#define DHEAD  64
#define MTOT   (NBATCH*SEQ)     // 8192
#define LSCALE 2.0f

// ---------------- scratch (device globals; no allocation allowed) ----------------
static __device__ uint32_t g_w  [3u*HID*HID];                          // folded weights, tf32 bits
static __device__ uint32_t g_x  [(size_t)MTOT*HID];                    // x in tf32 bits
static __device__ uint32_t g_qkv[(size_t)3*NBATCH*NHEAD*SEQ*DHEAD];    // tf32 [proj][b][h][t][d]

// ---------------- helpers ----------------
__device__ __forceinline__ uint32_t f2tf(float f){
    uint32_t u; asm("cvt.rna.tf32.f32 %0,%1;" : "=r"(u) : "f"(f)); return u;
}
__device__ __forceinline__ void cp16(uint32_t d, const void* s){
    asm volatile("cp.async.cg.shared.global [%0],[%1],16;" :: "r"(d), "l"(s));
}
__device__ __forceinline__ void cpcommit(){ asm volatile("cp.async.commit_group;"); }
__device__ __forceinline__ void cpwait0(){ asm volatile("cp.async.wait_group 0;"); }
__device__ __forceinline__ void cpwait1(){ asm volatile("cp.async.wait_group 1;"); }

__device__ __forceinline__ void mma8(float* c, uint32_t a0,uint32_t a1,uint32_t a2,uint32_t a3,
                                     uint32_t b0, uint32_t b1){
    asm volatile("mma.sync.aligned.m16n8k8.row.col.f32.tf32.tf32.f32 "
                 "{%0,%1,%2,%3},{%4,%5,%6,%7},{%8,%9},{%0,%1,%2,%3};"
                 : "+f"(c[0]),"+f"(c[1]),"+f"(c[2]),"+f"(c[3])
                 : "r"(a0),"r"(a1),"r"(a2),"r"(a3),"r"(b0),"r"(b1));
}

// ---------------- kernel 1: fold LoRA into weights (all 3 projections) ----------------
__global__ void fold_k(const float* __restrict__ Wq, const float* __restrict__ Aq, const float* __restrict__ Bq,
                       const float* __restrict__ Wk, const float* __restrict__ Ak, const float* __restrict__ Bk,
                       const float* __restrict__ Wv, const float* __restrict__ Av, const float* __restrict__ Bv){
    int gi = blockIdx.x*256 + threadIdx.x;           // over 3*1024*1024
    int proj = gi >> 20;
    int idx  = gi & 0xFFFFF;
    const float* W = (proj==0)?Wq:(proj==1)?Wk:Wv;
    const float* A = (proj==0)?Aq:(proj==1)?Ak:Av;
    const float* Bm= (proj==0)?Bq:(proj==1)?Bk:Bv;
    int o = idx >> 10, i = idx & 1023;
    float acc = 0.f;
#pragma unroll
    for (int r = 0; r < 8; r++) acc += Bm[o*8 + r] * A[r*1024 + i];
    g_w[(size_t)proj*HID*HID + idx] = f2tf(W[idx] + LSCALE*acc);
}

// ---------------- kernel 2: convert x to tf32 ----------------
__global__ void cvtx_k(const float4* __restrict__ x){
    int idx = blockIdx.x*256 + threadIdx.x;          // over MTOT*HID/4
    float4 v = x[idx];
    uint4 u; u.x=f2tf(v.x); u.y=f2tf(v.y); u.z=f2tf(v.z); u.w=f2tf(v.w);
    reinterpret_cast<uint4*>(g_x)[idx] = u;
}

// ---------------- kernel 3: QKV GEMM  C[m][o] = x * W_eff^T + b ----------------
// M=8192, N=3072, K=1024. CTA tile 128(M)x256(N), K-chunk 32, 3-stage cp.async
// pipeline, one __syncthreads per chunk. 512 threads, 16 warps as 4x4,
// warp tile 32x64. Halves L2 fill traffic vs 128x128 (A read 12x, B read 64x).
#define SAST 36                    // smem row stride (words); stride%32==4 -> conflict-free
#define ASTG (128*SAST)            // A tile words
#define GSTW ((128+256)*SAST)      // words per stage = 13824 (55296 B)
__global__ __launch_bounds__(512,1) void gemm_k(const float* __restrict__ bq,
                                                const float* __restrict__ bk,
                                                const float* __restrict__ bv){
    extern __shared__ uint32_t sm[];
    const int tid  = threadIdx.x;
    const int lane = tid & 31;
    const int wid  = tid >> 5;
    const int grp  = lane >> 2, tig = lane & 3;
    const int m0 = blockIdx.x*128, n0 = blockIdx.y*256;
    const int wm = (wid>>2)*32, wn = (wid&3)*64;
    unsigned sb = (unsigned)__cvta_generic_to_shared(sm);
    const uint32_t* gA = g_x + (size_t)m0*HID;
    const uint32_t* gB = g_w + (size_t)n0*HID;

    float c[2][8][4];
#pragma unroll
    for (int a=0;a<2;a++)
#pragma unroll
      for (int b2=0;b2<8;b2++)
#pragma unroll
        for (int i=0;i<4;i++) c[a][b2][i]=0.f;

    const int lrow = tid >> 3;          // 0..63
    const int lq4  = (tid & 7) * 4;     // 0..28

    auto load_tile = [&](int kt, int st){
        unsigned base = sb + (unsigned)(st*GSTW)*4;
#pragma unroll
        for (int i=0;i<2;i++){          // A: 128 rows
            int r = lrow + i*64;
            cp16(base + (unsigned)(r*SAST + lq4)*4, gA + (size_t)r*HID + kt*32 + lq4);
        }
#pragma unroll
        for (int i=0;i<4;i++){          // B: 256 rows
            int r = lrow + i*64;
            cp16(base + (unsigned)((ASTG + r*SAST + lq4))*4, gB + (size_t)r*HID + kt*32 + lq4);
        }
    };
    auto compute = [&](int st){
        const uint32_t* Ab = sm + st*GSTW;
        const uint32_t* Bb = Ab + ASTG;
#pragma unroll
        for (int ks=0; ks<4; ks++){
            int k = ks*8;
            uint32_t af[2][4], bf[8][2];
#pragma unroll
            for (int mt=0; mt<2; mt++){
                const uint32_t* p = Ab + (wm + mt*16 + grp)*SAST + k + tig;
                af[mt][0]=p[0]; af[mt][1]=p[8*SAST]; af[mt][2]=p[4]; af[mt][3]=p[8*SAST+4];
            }
#pragma unroll
            for (int nt=0; nt<8; nt++){
                const uint32_t* p = Bb + (wn + nt*8 + grp)*SAST + k + tig;
                bf[nt][0]=p[0]; bf[nt][1]=p[4];
            }
#pragma unroll
            for (int mt=0; mt<2; mt++)
#pragma unroll
                for (int nt=0; nt<8; nt++)
                    mma8(c[mt][nt], af[mt][0],af[mt][1],af[mt][2],af[mt][3], bf[nt][0],bf[nt][1]);
        }
    };

    load_tile(0,0); cpcommit();
    load_tile(1,1); cpcommit();
#pragma unroll 1
    for (int kt=0; kt<32; kt++){
        cpwait1();
        __syncthreads();                 // tile kt visible; stage (kt+2)%3 free
        if (kt+2 < 32) load_tile(kt+2, (kt+2)%3);
        cpcommit();                      // empty tail groups keep counts uniform
        compute(kt%3);
    }

    // epilogue: +bias, scatter to g_qkv as tf32
    const int proj = n0 >> 10;           // 256-tiles never straddle a projection
    const float* bias = (proj==0) ? bq : (proj==1 ? bk : bv);
#pragma unroll
    for (int mt=0; mt<2; mt++){
#pragma unroll
        for (int nt=0; nt<8; nt++){
            int n  = n0 + wn + nt*8 + 2*tig;
            int oo = n & 1023, hh = oo >> 6, dd = oo & 63;
            float bi0 = bias[oo], bi1 = bias[oo+1];
#pragma unroll
            for (int half=0; half<2; half++){
                int m = m0 + wm + mt*16 + grp + half*8;
                int bb = m >> 11, tt = m & 2047;
                size_t off = ((((size_t)proj*NBATCH + bb)*NHEAD + hh)*SEQ + tt)*DHEAD + dd;
                uint2 st2;
                st2.x = f2tf(c[mt][nt][half*2+0] + bi0);
                st2.y = f2tf(c[mt][nt][half*2+1] + bi1);
                *reinterpret_cast<uint2*>(g_qkv + off) = st2;
            }
        }
    }
}

// ---------------- kernel 4: causal flash attention ----------------
// One (b,h) x 128 q-rows per CTA. 8 warps x 16 q-rows. Bc=64 loads, double-
// buffered K/V; each tile is PROCESSED in two 32-col halves so the score
// array is s[4][4] (16 regs) -> no spills at the 128-reg/2-CTA cap.
// Q lives in registers; the Q smem region is reused as the P buffer.
#define PAST 68   // smem row stride (words); stride%32==4 -> conflict-free
__global__ __launch_bounds__(256,2) void attn_k(const float* __restrict__ mask,
                                                float* __restrict__ out){
    extern __shared__ uint32_t sm[];
    uint32_t* QP = sm;                    // [128][PAST] : Q first, then reused as P
    uint32_t* Ks = QP + 128*PAST;         // [2][64][PAST]
    uint32_t* Vs = Ks + 2*64*PAST;        // [2][64][PAST]
    unsigned sQ = (unsigned)__cvta_generic_to_shared(QP);
    unsigned sK = (unsigned)__cvta_generic_to_shared(Ks);
    unsigned sV = (unsigned)__cvta_generic_to_shared(Vs);

    const int tid = threadIdx.x, lane = tid & 31, wid = tid >> 5;
    const int grp = lane >> 2, tig = lane & 3;
    const int bh = blockIdx.x;
    const int qb = 15 - blockIdx.y;       // heaviest blocks launch first
    const int b = bh >> 4, h = bh & 15;

    const uint32_t* Qg = g_qkv + ((size_t)(0*64 + bh)*SEQ + qb*128)*DHEAD;
    const uint32_t* Kg = g_qkv + ((size_t)(1*64 + bh)*SEQ)*DHEAD;
    const uint32_t* Vg = g_qkv + ((size_t)(2*64 + bh)*SEQ)*DHEAD;
    const float* mrow = mask + (size_t)b*SEQ;

    // Q -> smem (group 0)
    {
        int r = tid >> 4, q4 = (tid & 15)*4;
#pragma unroll
        for (int i=0;i<8;i++){
            int rr = r + i*16;
            cp16(sQ + (unsigned)(rr*PAST + q4)*4, Qg + (size_t)rr*64 + q4);
        }
    }
    cpcommit();
    auto loadkv = [&](int j, int st){
        int r = tid >> 4, q4 = (tid & 15)*4;
#pragma unroll
        for (int i=0;i<4;i++){
            int rr = r + i*16;
            cp16(sK + (unsigned)((st*64 + rr)*PAST + q4)*4, Kg + (size_t)(j*64 + rr)*64 + q4);
            cp16(sV + (unsigned)((st*64 + rr)*PAST + q4)*4, Vg + (size_t)(j*64 + rr)*64 + q4);
        }
    };
    loadkv(0,0); cpcommit();              // group 1

    // wait for Q (group 0), publish, pull Q fragments into registers
    cpwait1();
    __syncthreads();
    uint32_t qf[8][4];
#pragma unroll
    for (int kg=0; kg<8; kg++){
        const uint32_t* qp = QP + (wid*16 + grp)*PAST + kg*8 + tig;
        qf[kg][0]=qp[0]; qf[kg][1]=qp[8*PAST]; qf[kg][2]=qp[4]; qf[kg][3]=qp[8*PAST+4];
    }
    // From here QP is the P buffer; each warp touches only its own 16 rows.

    const int qrow0 = qb*128 + wid*16;
    float mr0 = -1e30f, mr1 = -1e30f, l0 = 0.f, l1 = 0.f;
    float o[8][4];
#pragma unroll
    for (int nt=0;nt<8;nt++)
#pragma unroll
        for (int i=0;i<4;i++) o[nt][i]=0.f;

    const int nj = 2*qb + 2;
#pragma unroll 1
    for (int j=0; j<nj; j++){
        if (j+1 < nj){ loadkv(j+1,(j+1)&1); cpcommit(); cpwait1(); }
        else cpwait0();
        __syncthreads();

        const uint32_t* Kb = Ks + (j&1)*64*PAST;
        const uint32_t* Vb = Vs + (j&1)*64*PAST;
        const int q0 = qrow0 + grp, q1 = q0 + 8;

#pragma unroll
        for (int half=0; half<2; half++){
            const int c0 = j*64 + half*32;
            if (c0 > qrow0 + 15) break;   // fully masked half (and the next)

            float s[4][4];
#pragma unroll
            for (int nt=0;nt<4;nt++)
#pragma unroll
                for (int i=0;i<4;i++) s[nt][i]=0.f;

            // S = Q K^T  (32 kv cols)
#pragma unroll
            for (int ks=0; ks<8; ks++){
                int k = ks*8;
#pragma unroll
                for (int nt=0; nt<4; nt++){
                    const uint32_t* kp = Kb + (half*32 + nt*8 + grp)*PAST + k + tig;
                    mma8(s[nt], qf[ks][0],qf[ks][1],qf[ks][2],qf[ks][3], kp[0], kp[4]);
                }
            }
            // scale + mask + online softmax
            float mx0 = -1e30f, mx1 = -1e30f;
#pragma unroll
            for (int nt=0; nt<4; nt++){
                int sc = c0 + nt*8 + 2*tig;
                float mk0 = __ldg(mrow + sc), mk1 = __ldg(mrow + sc + 1);
                float v0 = s[nt][0]*0.125f + mk0; if (sc   > q0) v0 = -1e30f;
                float v1 = s[nt][1]*0.125f + mk1; if (sc+1 > q0) v1 = -1e30f;
                float v2 = s[nt][2]*0.125f + mk0; if (sc   > q1) v2 = -1e30f;
                float v3 = s[nt][3]*0.125f + mk1; if (sc+1 > q1) v3 = -1e30f;
                s[nt][0]=v0; s[nt][1]=v1; s[nt][2]=v2; s[nt][3]=v3;
                mx0 = fmaxf(mx0, fmaxf(v0,v1));
                mx1 = fmaxf(mx1, fmaxf(v2,v3));
            }
            mx0 = fmaxf(mx0, __shfl_xor_sync(0xffffffffu, mx0, 1));
            mx0 = fmaxf(mx0, __shfl_xor_sync(0xffffffffu, mx0, 2));
            mx1 = fmaxf(mx1, __shfl_xor_sync(0xffffffffu, mx1, 1));
            mx1 = fmaxf(mx1, __shfl_xor_sync(0xffffffffu, mx1, 2));
            float mn0 = fmaxf(mr0, mx0), mn1 = fmaxf(mr1, mx1);
            float al0 = __expf(mr0 - mn0), al1 = __expf(mr1 - mn1);
            mr0 = mn0; mr1 = mn1;

            float ps0 = 0.f, ps1 = 0.f;
            uint32_t* pw = QP + (wid*16 + grp)*PAST + 2*tig;
#pragma unroll
            for (int nt=0; nt<4; nt++){
                float p0 = __expf(s[nt][0]-mn0), p1 = __expf(s[nt][1]-mn0);
                float p2 = __expf(s[nt][2]-mn1), p3 = __expf(s[nt][3]-mn1);
                ps0 += p0 + p1; ps1 += p2 + p3;
                uint2 u0; u0.x = f2tf(p0); u0.y = f2tf(p1);
                uint2 u1; u1.x = f2tf(p2); u1.y = f2tf(p3);
                *reinterpret_cast<uint2*>(pw + nt*8)          = u0;
                *reinterpret_cast<uint2*>(pw + 8*PAST + nt*8) = u1;
            }
            ps0 += __shfl_xor_sync(0xffffffffu, ps0, 1);
            ps0 += __shfl_xor_sync(0xffffffffu, ps0, 2);
            ps1 += __shfl_xor_sync(0xffffffffu, ps1, 1);
            ps1 += __shfl_xor_sync(0xffffffffu, ps1, 2);
            l0 = l0*al0 + ps0; l1 = l1*al1 + ps1;
#pragma unroll
            for (int nt=0; nt<8; nt++){
                o[nt][0]*=al0; o[nt][1]*=al0; o[nt][2]*=al1; o[nt][3]*=al1;
            }
            __syncwarp();

            // O += P V  (32 kv rows of this half)
#pragma unroll
            for (int kc=0; kc<4; kc++){
                int k = kc*8;
                const uint32_t* pp = QP + (wid*16 + grp)*PAST + k + tig;
                uint32_t a0=pp[0], a1=pp[8*PAST], a2=pp[4], a3=pp[8*PAST+4];
#pragma unroll
                for (int nt=0; nt<8; nt++){
                    const uint32_t* vp = Vb + (half*32 + k + tig)*PAST + nt*8 + grp;
                    mma8(o[nt], a0,a1,a2,a3, vp[0], vp[4*PAST]);
                }
            }
            __syncwarp();                 // P reads done before next half rewrites
        }
        __syncthreads();
    }

    // epilogue: normalize + store out[b][t][h*64+d]
    float i0 = 1.f/l0, i1 = 1.f/l1;
    int t0 = qrow0 + grp, t1 = t0 + 8;
    float* o0 = out + ((size_t)b*SEQ + t0)*HID + h*64;
    float* o1 = out + ((size_t)b*SEQ + t1)*HID + h*64;
#pragma unroll
    for (int nt=0; nt<8; nt++){
        int d = nt*8 + 2*tig;
        float2 f0; f0.x = o[nt][0]*i0; f0.y = o[nt][1]*i0;
        float2 f1; f1.x = o[nt][2]*i1; f1.y = o[nt][3]*i1;
        *reinterpret_cast<float2*>(o0 + d) = f0;
        *reinterpret_cast<float2*>(o1 + d) = f1;
    }
}

// ---------------- launch ----------------
extern "C" void kernel_launch(void* const* d_in, const int* in_sizes, int n_in,
                              void* d_out, int out_size){
    const float* x    = (const float*)d_in[0];
    const float* mask = (const float*)d_in[1];
    const float* Wq=(const float*)d_in[2],  *bq=(const float*)d_in[3];
    const float* Aq=(const float*)d_in[4],  *Bq=(const float*)d_in[5];
    const float* Wk=(const float*)d_in[6],  *bk=(const float*)d_in[7];
    const float* Ak=(const float*)d_in[8],  *Bk=(const float*)d_in[9];
    const float* Wv=(const float*)d_in[10], *bv=(const float*)d_in[11];
    const float* Av=(const float*)d_in[12], *Bv=(const float*)d_in[13];

    fold_k<<<12288,256>>>(Wq,Aq,Bq, Wk,Ak,Bk, Wv,Av,Bv);
    cvtx_k<<<8192,256>>>((const float4*)x);

    const int gemm_smem = 3*GSTW*4;                           // 165888 B
    cudaFuncSetAttribute(gemm_k, cudaFuncAttributeMaxDynamicSharedMemorySize, gemm_smem);
    gemm_k<<<dim3(64,12),512,gemm_smem>>>(bq,bk,bv);

    const int attn_smem = (128*PAST + 4*64*PAST)*4;           // 104448 B
    cudaFuncSetAttribute(attn_k, cudaFuncAttributeMaxDynamicSharedMemorySize, attn_smem);
    attn_k<<<dim3(64,16),256,attn_smem>>>(mask, (float*)d_out);
}